// round 5
// baseline (speedup 1.0000x reference)
#include <cuda_runtime.h>

#define TT 512
#define BB 1024
#define NN 64
#define NWARPS 592   // 148 CTAs * 4 warps
#define GRID 148

__device__ float g_partial[BB];
__device__ int g_count = 0;

typedef unsigned long long ull;

// ---- packed f32x2 helpers (Blackwell) ----
__device__ __forceinline__ ull pack2(float x, float y) {
    ull r; asm("mov.b64 %0, {%1, %2};" : "=l"(r) : "f"(x), "f"(y)); return r;
}
__device__ __forceinline__ void unpack2(ull v, float& x, float& y) {
    asm("mov.b64 {%0, %1}, %2;" : "=f"(x), "=f"(y) : "l"(v));
}
__device__ __forceinline__ ull fma2(ull a, ull b, ull c) {
    ull d; asm("fma.rn.f32x2 %0, %1, %2, %3;" : "=l"(d) : "l"(a), "l"(b), "l"(c)); return d;
}
__device__ __forceinline__ ull add2(ull a, ull b) {
    ull d; asm("add.rn.f32x2 %0, %1, %2;" : "=l"(d) : "l"(a), "l"(b)); return d;
}

__device__ __forceinline__ int seq_len(const void* mask_raw, int mmode, int b, int lane) {
    const unsigned char* m8 = (const unsigned char*)mask_raw;
    const int* m32 = (const int*)mask_raw;
    const float* mf = (const float*)mask_raw;
    int len = 0;
    if (mmode == 0) {
#pragma unroll 4
        for (int t = lane; t < TT; t += 32) len += (m8[(size_t)t * BB + b] != 0);
    } else if (mmode == 1) {
#pragma unroll 4
        for (int t = lane; t < TT; t += 32) len += (m32[(size_t)t * BB + b] != 0);
    } else {
#pragma unroll 4
        for (int t = lane; t < TT; t += 32) len += (mf[(size_t)t * BB + b] != 0.0f);
    }
#pragma unroll
    for (int o = 16; o; o >>= 1) len += __shfl_xor_sync(0xffffffffu, len, o);
    return len;
}

// gold-path score; result valid on lane 0
__device__ __forceinline__ float gold_score(
    const float* __restrict__ emit, const float* __restrict__ trans,
    const float* __restrict__ strans, const float* __restrict__ etrans,
    const void* __restrict__ traw, int tmode, int b, int len, int lane)
{
    const int* t32 = (const int*)traw;
    const long long* t64 = (const long long*)traw;
    float sc = 0.f;
    for (int i = lane; i < len; i += 32) {
        size_t idx = (size_t)i * BB + b;
        int tg = tmode ? (int)t64[idx] : t32[idx];
        sc += emit[idx * NN + tg];
        if (i > 0) {
            size_t p = (size_t)(i - 1) * BB + b;
            int pg = tmode ? (int)t64[p] : t32[p];
            sc += trans[pg * NN + tg];
        }
    }
#pragma unroll
    for (int o = 16; o; o >>= 1) sc += __shfl_xor_sync(0xffffffffu, sc, o);
    if (lane == 0) {
        int tg0 = tmode ? (int)t64[b] : t32[b];
        size_t li = (size_t)(len - 1) * BB + b;
        int tgl = tmode ? (int)t64[li] : t32[li];
        sc += strans[tg0] + etrans[tgl];
    }
    return sc;
}

__device__ __forceinline__ float logZ_of(float a0, float a1, float2 et) {
    float v0 = a0 + et.x, v1 = a1 + et.y;
    float m = fmaxf(v0, v1);
#pragma unroll
    for (int o = 16; o; o >>= 1) m = fmaxf(m, __shfl_xor_sync(0xffffffffu, m, o));
    float s = __expf(v0 - m) + __expf(v1 - m);
#pragma unroll
    for (int o = 16; o; o >>= 1) s += __shfl_xor_sync(0xffffffffu, s, o);
    return m + __logf(s);
}

__global__ void __launch_bounds__(128, 1) crf_fused_kernel(
    const float* __restrict__ emit,
    const float* __restrict__ trans,
    const float* __restrict__ strans,
    const float* __restrict__ etrans,
    const void* __restrict__ target_raw,
    const void* __restrict__ mask_raw,
    float* __restrict__ out)
{
    const int lane = threadIdx.x & 31;
    const int w = threadIdx.x >> 5;
    const int gw = blockIdx.x * 4 + w;
    const int b1 = gw;                 // always < BB
    const int b2 = NWARPS + gw;
    const bool has2 = (b2 < BB);

    // double-buffered per-warp, per-batch broadcast buffers of duplicated exp(alpha)
    __shared__ ulonglong2 sbuf[2][4][2][32];

    // ---- dtype self-detection (mask row 0 all-True since lengths >= 1) ----
    const unsigned char* m8 = (const unsigned char*)mask_raw;
    int mmode;  // 0 = u8, 1 = i32, 2 = f32
    if (m8[0] == 1 && m8[1] == 1)      mmode = 0;
    else if (m8[0] == 1)               mmode = 1;
    else                               mmode = 2;

    const int* t32p = (const int*)target_raw;
    int oddbits = 0;
#pragma unroll
    for (int i = 1; i < 16; i += 2) oddbits |= t32p[i];
    const int tmode = (oddbits == 0) ? 1 : 0;  // 1 = int64, 0 = int32

    // E columns in registers, packed: E2[j] = (exp(trans[j][2*lane]), exp(trans[j][2*lane+1]))
    ull E2[NN];
#pragma unroll
    for (int j = 0; j < NN; j++) {
        float2 tr = reinterpret_cast<const float2*>(trans)[j * 32 + lane];
        E2[j] = pack2(__expf(tr.x), __expf(tr.y));
    }

    const int len1 = seq_len(mask_raw, mmode, b1, lane);
    const int len2 = has2 ? seq_len(mask_raw, mmode, b2, lane) : 0;

    const float2* emit2 = reinterpret_cast<const float2*>(emit);
    float2 st = reinterpret_cast<const float2*>(strans)[lane];

    float2 e0 = emit2[(size_t)b1 * 32 + lane];
    float a0_1 = st.x + e0.x, a1_1 = st.y + e0.y;
    float a0_2 = 0.f, a1_2 = 0.f;
    if (has2) {
        float2 e0b = emit2[(size_t)b2 * 32 + lane];
        a0_2 = st.x + e0b.x;  a1_2 = st.y + e0b.y;
    }

    const int lmin = min(len1, len2);
    float2 en1 = emit2[((size_t)1 * BB + b1) * 32 + lane];                       // t=1 prefetch (always safe: TT>=2)
    float2 en2 = has2 ? emit2[((size_t)1 * BB + b2) * 32 + lane] : make_float2(0.f, 0.f);

    // ---- phase 1: both batches interleaved (ILP hides the recurrence latency) ----
    for (int t = 1; t < lmin; t++) {
        float2 ec1 = en1, ec2 = en2;
        int tn = min(t + 1, TT - 1);
        en1 = emit2[((size_t)tn * BB + b1) * 32 + lane];
        en2 = emit2[((size_t)tn * BB + b2) * 32 + lane];

        // stabilizing offset: any alpha component works (bounded cross-state spread)
        float M1 = __shfl_sync(0xffffffffu, a0_1, 0);
        float M2 = __shfl_sync(0xffffffffu, a0_2, 0);
        float e10 = __expf(a0_1 - M1), e11 = __expf(a1_1 - M1);
        float e20 = __expf(a0_2 - M2), e21 = __expf(a1_2 - M2);

        const int par = t & 1;
        sbuf[par][w][0][lane] = make_ulonglong2(pack2(e10, e10), pack2(e11, e11));
        sbuf[par][w][1][lane] = make_ulonglong2(pack2(e20, e20), pack2(e21, e21));
        __syncwarp();

        const ulonglong2* s1 = sbuf[par][w][0];
        const ulonglong2* s2 = sbuf[par][w][1];
        ull cA1 = 0, cB1 = 0, cC1 = 0, cD1 = 0;
        ull cA2 = 0, cB2 = 0, cC2 = 0, cD2 = 0;
#pragma unroll
        for (int s = 0; s < 32; s += 2) {
            ulonglong2 q0 = s1[s], q1 = s1[s + 1];
            ulonglong2 r0 = s2[s], r1 = s2[s + 1];
            cA1 = fma2(q0.x, E2[2 * s],     cA1);
            cA2 = fma2(r0.x, E2[2 * s],     cA2);
            cB1 = fma2(q0.y, E2[2 * s + 1], cB1);
            cB2 = fma2(r0.y, E2[2 * s + 1], cB2);
            cC1 = fma2(q1.x, E2[2 * s + 2], cC1);
            cC2 = fma2(r1.x, E2[2 * s + 2], cC2);
            cD1 = fma2(q1.y, E2[2 * s + 3], cD1);
            cD2 = fma2(r1.y, E2[2 * s + 3], cD2);
        }
        float cx1, cy1, cx2, cy2;
        unpack2(add2(add2(cA1, cB1), add2(cC1, cD1)), cx1, cy1);
        unpack2(add2(add2(cA2, cB2), add2(cC2, cD2)), cx2, cy2);
        a0_1 = M1 + __logf(cx1) + ec1.x;
        a1_1 = M1 + __logf(cy1) + ec1.y;
        a0_2 = M2 + __logf(cx2) + ec2.x;
        a1_2 = M2 + __logf(cy2) + ec2.y;
    }

    // ---- phase 2: survivor (longer) batch alone ----
    {
        const bool b1_surv = (len1 >= len2);
        float sa0 = b1_surv ? a0_1 : a0_2;
        float sa1 = b1_surv ? a1_1 : a1_2;
        const int sb   = b1_surv ? b1 : b2;
        const int slen = b1_surv ? len1 : len2;
        const int t0 = max(lmin, 1);
        // prime prefetch for start t0
        float2 en = emit2[((size_t)min(t0, TT - 1) * BB + sb) * 32 + lane];

        for (int t = t0; t < slen; t++) {
            float2 ec = en;
            int tn = min(t + 1, TT - 1);
            en = emit2[((size_t)tn * BB + sb) * 32 + lane];

            float M = __shfl_sync(0xffffffffu, sa0, 0);
            float ea0 = __expf(sa0 - M), ea1 = __expf(sa1 - M);
            const int par = t & 1;
            sbuf[par][w][0][lane] = make_ulonglong2(pack2(ea0, ea0), pack2(ea1, ea1));
            __syncwarp();

            const ulonglong2* sw = sbuf[par][w][0];
            ull cA = 0, cB = 0, cC = 0, cD = 0;
#pragma unroll
            for (int s = 0; s < 32; s += 2) {
                ulonglong2 q0 = sw[s], q1 = sw[s + 1];
                cA = fma2(q0.x, E2[2 * s],     cA);
                cB = fma2(q0.y, E2[2 * s + 1], cB);
                cC = fma2(q1.x, E2[2 * s + 2], cC);
                cD = fma2(q1.y, E2[2 * s + 3], cD);
            }
            float cx, cy;
            unpack2(add2(add2(cA, cB), add2(cC, cD)), cx, cy);
            sa0 = M + __logf(cx) + ec.x;
            sa1 = M + __logf(cy) + ec.y;
        }
        if (b1_surv) { a0_1 = sa0; a1_1 = sa1; }
        else         { a0_2 = sa0; a1_2 = sa1; }
    }

    // ---- logZ + gold score + partial store ----
    float2 et = reinterpret_cast<const float2*>(etrans)[lane];
    {
        float logZ1 = logZ_of(a0_1, a1_1, et);
        float sc1 = gold_score(emit, trans, strans, etrans, target_raw, tmode, b1, len1, lane);
        if (lane == 0) g_partial[b1] = logZ1 - sc1;
    }
    if (has2) {
        float logZ2 = logZ_of(a0_2, a1_2, et);
        float sc2 = gold_score(emit, trans, strans, etrans, target_raw, tmode, b2, len2, lane);
        if (lane == 0) g_partial[b2] = logZ2 - sc2;
    }

    // ---- last-CTA-done deterministic reduction ----
    __shared__ float rsh[128];
    __shared__ int islast;
    __threadfence();
    __syncthreads();
    if (threadIdx.x == 0)
        islast = (atomicAdd(&g_count, 1) == GRID - 1);
    __syncthreads();
    if (islast) {
        __threadfence();
        float s = 0.f;
#pragma unroll
        for (int i = 0; i < BB / 128; i++)          // fixed order: deterministic
            s += g_partial[threadIdx.x + i * 128];
        rsh[threadIdx.x] = s;
        __syncthreads();
        for (int off = 64; off > 0; off >>= 1) {
            if (threadIdx.x < off) rsh[threadIdx.x] += rsh[threadIdx.x + off];
            __syncthreads();
        }
        if (threadIdx.x == 0) {
            out[0] = rsh[0] * (1.0f / BB);
            g_count = 0;                            // reset for next graph replay
        }
    }
}

extern "C" void kernel_launch(void* const* d_in, const int* in_sizes, int n_in,
                              void* d_out, int out_size) {
    const float* emit   = (const float*)d_in[0];
    const float* trans  = (const float*)d_in[1];
    const float* strans = (const float*)d_in[2];
    const float* etrans = (const float*)d_in[3];
    const void* target  = d_in[4];
    const void* mask    = d_in[5];

    crf_fused_kernel<<<GRID, 128>>>(emit, trans, strans, etrans, target, mask,
                                    (float*)d_out);
}

// round 6
// speedup vs baseline: 1.0908x; 1.0908x over previous
#include <cuda_runtime.h>

#define TT 512
#define BB 1024
#define NN 64
#define GRID 256
#define PD 4

__device__ float g_partial[BB];
__device__ int g_count = 0;

typedef unsigned long long ull;

// ---- packed f32x2 helpers (Blackwell) ----
__device__ __forceinline__ ull pack2(float x, float y) {
    ull r; asm("mov.b64 %0, {%1, %2};" : "=l"(r) : "f"(x), "f"(y)); return r;
}
__device__ __forceinline__ void unpack2(ull v, float& x, float& y) {
    asm("mov.b64 {%0, %1}, %2;" : "=f"(x), "=f"(y) : "l"(v));
}
__device__ __forceinline__ ull fma2(ull a, ull b, ull c) {
    ull d; asm("fma.rn.f32x2 %0, %1, %2, %3;" : "=l"(d) : "l"(a), "l"(b), "l"(c)); return d;
}
__device__ __forceinline__ ull add2(ull a, ull b) {
    ull d; asm("add.rn.f32x2 %0, %1, %2;" : "=l"(d) : "l"(a), "l"(b)); return d;
}

__device__ __forceinline__ int seq_len(const void* mask_raw, int mmode, int b, int lane) {
    const unsigned char* m8 = (const unsigned char*)mask_raw;
    const int* m32 = (const int*)mask_raw;
    const float* mf = (const float*)mask_raw;
    int len = 0;
    if (mmode == 0) {
#pragma unroll 4
        for (int t = lane; t < TT; t += 32) len += (m8[(size_t)t * BB + b] != 0);
    } else if (mmode == 1) {
#pragma unroll 4
        for (int t = lane; t < TT; t += 32) len += (m32[(size_t)t * BB + b] != 0);
    } else {
#pragma unroll 4
        for (int t = lane; t < TT; t += 32) len += (mf[(size_t)t * BB + b] != 0.0f);
    }
#pragma unroll
    for (int o = 16; o; o >>= 1) len += __shfl_xor_sync(0xffffffffu, len, o);
    return len;
}

// gold-path score; result valid on lane 0
__device__ __forceinline__ float gold_score(
    const float* __restrict__ emit, const float* __restrict__ trans,
    const float* __restrict__ strans, const float* __restrict__ etrans,
    const void* __restrict__ traw, int tmode, int b, int len, int lane)
{
    const int* t32 = (const int*)traw;
    const long long* t64 = (const long long*)traw;
    float sc = 0.f;
    for (int i = lane; i < len; i += 32) {
        size_t idx = (size_t)i * BB + b;
        int tg = tmode ? (int)t64[idx] : t32[idx];
        sc += emit[idx * NN + tg];
        if (i > 0) {
            size_t p = (size_t)(i - 1) * BB + b;
            int pg = tmode ? (int)t64[p] : t32[p];
            sc += trans[pg * NN + tg];
        }
    }
#pragma unroll
    for (int o = 16; o; o >>= 1) sc += __shfl_xor_sync(0xffffffffu, sc, o);
    if (lane == 0) {
        int tg0 = tmode ? (int)t64[b] : t32[b];
        size_t li = (size_t)(len - 1) * BB + b;
        int tgl = tmode ? (int)t64[li] : t32[li];
        sc += strans[tg0] + etrans[tgl];
    }
    return sc;
}

__global__ void __launch_bounds__(128, 2) crf_fused_kernel(
    const float* __restrict__ emit,
    const float* __restrict__ trans,
    const float* __restrict__ strans,
    const float* __restrict__ etrans,
    const void* __restrict__ target_raw,
    const void* __restrict__ mask_raw,
    float* __restrict__ out)
{
    const int lane = threadIdx.x & 31;
    const int w = threadIdx.x >> 5;
    const int b = blockIdx.x * 4 + w;        // GRID*4 == BB, exactly one batch/warp

    // double-buffered per-warp broadcast of duplicated exp(alpha)
    __shared__ ulonglong2 sbuf[2][4][32];

    // ---- dtype self-detection (mask row 0 all-True since lengths >= 1) ----
    const unsigned char* m8 = (const unsigned char*)mask_raw;
    int mmode;  // 0 = u8, 1 = i32, 2 = f32
    if (m8[0] == 1 && m8[1] == 1)      mmode = 0;
    else if (m8[0] == 1)               mmode = 1;
    else                               mmode = 2;

    const int* t32p = (const int*)target_raw;
    int oddbits = 0;
#pragma unroll
    for (int i = 1; i < 16; i += 2) oddbits |= t32p[i];
    const int tmode = (oddbits == 0) ? 1 : 0;  // 1 = int64, 0 = int32

    // E columns in registers, packed: E2[j] = (exp(trans[j][2*lane]), exp(trans[j][2*lane+1]))
    ull E2[NN];
#pragma unroll
    for (int j = 0; j < NN; j++) {
        float2 tr = reinterpret_cast<const float2*>(trans)[j * 32 + lane];
        E2[j] = pack2(__expf(tr.x), __expf(tr.y));
    }

    const int len = seq_len(mask_raw, mmode, b, lane);

    const float2* emit2 = reinterpret_cast<const float2*>(emit);
    float2 st = reinterpret_cast<const float2*>(strans)[lane];
    float2 e0 = emit2[(size_t)b * 32 + lane];
    float a0 = st.x + e0.x;   // alpha[2*lane]
    float a1 = st.y + e0.y;   // alpha[2*lane+1]

    // 4-deep register prefetch ring for the emit stream (hides DRAM latency)
    float2 q[PD];
#pragma unroll
    for (int j = 0; j < PD; j++)
        q[j] = emit2[((size_t)min(1 + j, TT - 1) * BB + b) * 32 + lane];

    // Stabilizing offset, lag-2: M used at step t is shfl of a0 from step t-2,
    // issued one full step early so the shfl latency is off the critical chain.
    // Algebraically exact (any offset works); drift over 2 steps stays << exp range.
    float Mcur = __shfl_sync(0xffffffffu, a0, 0);
    float Mnext = Mcur;

#define CRF_STEP(EC, TIDX)                                                     \
    {                                                                          \
        float ea0 = __expf(a0 - Mcur), ea1 = __expf(a1 - Mcur);                \
        const int par = (TIDX) & 1;                                            \
        sbuf[par][w][lane] = make_ulonglong2(pack2(ea0, ea0), pack2(ea1, ea1));\
        __syncwarp();                                                          \
        const ulonglong2* swp = sbuf[par][w];                                  \
        ull cA = 0, cB = 0, cC = 0, cD = 0;                                    \
        _Pragma("unroll")                                                      \
        for (int s = 0; s < 32; s += 2) {                                      \
            ulonglong2 u0 = swp[s], u1 = swp[s + 1];                           \
            cA = fma2(u0.x, E2[2 * s],     cA);                                \
            cB = fma2(u0.y, E2[2 * s + 1], cB);                                \
            cC = fma2(u1.x, E2[2 * s + 2], cC);                                \
            cD = fma2(u1.y, E2[2 * s + 3], cD);                                \
        }                                                                      \
        float cx, cy;                                                          \
        unpack2(add2(add2(cA, cB), add2(cC, cD)), cx, cy);                     \
        a0 = Mcur + __logf(cx) + (EC).x;                                       \
        a1 = Mcur + __logf(cy) + (EC).y;                                       \
        Mcur = Mnext;                                                          \
        Mnext = __shfl_sync(0xffffffffu, a0, 0);                               \
    }

    int t = 1;
    for (; t + PD <= len; t += PD) {
#pragma unroll
        for (int j = 0; j < PD; j++) {
            float2 ec = q[j];
            q[j] = emit2[((size_t)min(t + PD + j, TT - 1) * BB + b) * 32 + lane];
            CRF_STEP(ec, t + j);
        }
    }
    for (int j = 0; t < len; t++, j++) {   // tail: q[j] holds slot t
        float2 ec = q[j];
        CRF_STEP(ec, t);
    }
#undef CRF_STEP

    // logZ_b = logsumexp_k(alpha_k + etrans_k)
    float2 et = reinterpret_cast<const float2*>(etrans)[lane];
    float v0 = a0 + et.x, v1 = a1 + et.y;
    float m = fmaxf(v0, v1);
#pragma unroll
    for (int o = 16; o; o >>= 1) m = fmaxf(m, __shfl_xor_sync(0xffffffffu, m, o));
    float s2 = __expf(v0 - m) + __expf(v1 - m);
#pragma unroll
    for (int o = 16; o; o >>= 1) s2 += __shfl_xor_sync(0xffffffffu, s2, o);
    float logZ = m + __logf(s2);

    float sc = gold_score(emit, trans, strans, etrans, target_raw, tmode, b, len, lane);
    if (lane == 0) g_partial[b] = logZ - sc;

    // ---- last-CTA-done deterministic reduction ----
    __shared__ float rsh[128];
    __shared__ int islast;
    __threadfence();
    __syncthreads();
    if (threadIdx.x == 0)
        islast = (atomicAdd(&g_count, 1) == GRID - 1);
    __syncthreads();
    if (islast) {
        __threadfence();
        float s = 0.f;
#pragma unroll
        for (int i = 0; i < BB / 128; i++)          // fixed order: deterministic
            s += g_partial[threadIdx.x + i * 128];
        rsh[threadIdx.x] = s;
        __syncthreads();
        for (int off = 64; off > 0; off >>= 1) {
            if (threadIdx.x < off) rsh[threadIdx.x] += rsh[threadIdx.x + off];
            __syncthreads();
        }
        if (threadIdx.x == 0) {
            out[0] = rsh[0] * (1.0f / BB);
            g_count = 0;                            // reset for next graph replay
        }
    }
}

extern "C" void kernel_launch(void* const* d_in, const int* in_sizes, int n_in,
                              void* d_out, int out_size) {
    const float* emit   = (const float*)d_in[0];
    const float* trans  = (const float*)d_in[1];
    const float* strans = (const float*)d_in[2];
    const float* etrans = (const float*)d_in[3];
    const void* target  = d_in[4];
    const void* mask    = d_in[5];

    crf_fused_kernel<<<GRID, 128>>>(emit, trans, strans, etrans, target, mask,
                                    (float*)d_out);
}

// round 7
// speedup vs baseline: 1.0916x; 1.0007x over previous
#include <cuda_runtime.h>

#define TT 512
#define BB 1024
#define NN 64
#define GRID 256
#define PD 4

__device__ float g_partial[BB];
__device__ int g_count = 0;

typedef unsigned long long ull;

// ---- packed f32x2 helpers (Blackwell) ----
__device__ __forceinline__ ull pack2(float x, float y) {
    ull r; asm("mov.b64 %0, {%1, %2};" : "=l"(r) : "f"(x), "f"(y)); return r;
}
__device__ __forceinline__ void unpack2(ull v, float& x, float& y) {
    asm("mov.b64 {%0, %1}, %2;" : "=f"(x), "=f"(y) : "l"(v));
}
__device__ __forceinline__ ull fma2(ull a, ull b, ull c) {
    ull d; asm("fma.rn.f32x2 %0, %1, %2, %3;" : "=l"(d) : "l"(a), "l"(b), "l"(c)); return d;
}
__device__ __forceinline__ ull add2(ull a, ull b) {
    ull d; asm("add.rn.f32x2 %0, %1, %2;" : "=l"(d) : "l"(a), "l"(b)); return d;
}
__device__ __forceinline__ ull mul2(ull a, ull b) {
    ull d; asm("mul.rn.f32x2 %0, %1, %2;" : "=l"(d) : "l"(a), "l"(b)); return d;
}

__device__ __forceinline__ int seq_len(const void* mask_raw, int mmode, int b, int lane) {
    const unsigned char* m8 = (const unsigned char*)mask_raw;
    const int* m32 = (const int*)mask_raw;
    const float* mf = (const float*)mask_raw;
    int len = 0;
    if (mmode == 0) {
#pragma unroll 4
        for (int t = lane; t < TT; t += 32) len += (m8[(size_t)t * BB + b] != 0);
    } else if (mmode == 1) {
#pragma unroll 4
        for (int t = lane; t < TT; t += 32) len += (m32[(size_t)t * BB + b] != 0);
    } else {
#pragma unroll 4
        for (int t = lane; t < TT; t += 32) len += (mf[(size_t)t * BB + b] != 0.0f);
    }
#pragma unroll
    for (int o = 16; o; o >>= 1) len += __shfl_xor_sync(0xffffffffu, len, o);
    return len;
}

// gold-path score; result valid on lane 0
__device__ __forceinline__ float gold_score(
    const float* __restrict__ emit, const float* __restrict__ trans,
    const float* __restrict__ strans, const float* __restrict__ etrans,
    const void* __restrict__ traw, int tmode, int b, int len, int lane)
{
    const int* t32 = (const int*)traw;
    const long long* t64 = (const long long*)traw;
    float sc = 0.f;
    for (int i = lane; i < len; i += 32) {
        size_t idx = (size_t)i * BB + b;
        int tg = tmode ? (int)t64[idx] : t32[idx];
        sc += emit[idx * NN + tg];
        if (i > 0) {
            size_t p = (size_t)(i - 1) * BB + b;
            int pg = tmode ? (int)t64[p] : t32[p];
            sc += trans[pg * NN + tg];
        }
    }
#pragma unroll
    for (int o = 16; o; o >>= 1) sc += __shfl_xor_sync(0xffffffffu, sc, o);
    if (lane == 0) {
        int tg0 = tmode ? (int)t64[b] : t32[b];
        size_t li = (size_t)(len - 1) * BB + b;
        int tgl = tmode ? (int)t64[li] : t32[li];
        sc += strans[tg0] + etrans[tgl];
    }
    return sc;
}

__global__ void __launch_bounds__(128, 2) crf_fused_kernel(
    const float* __restrict__ emit,
    const float* __restrict__ trans,
    const float* __restrict__ strans,
    const float* __restrict__ etrans,
    const void* __restrict__ target_raw,
    const void* __restrict__ mask_raw,
    float* __restrict__ out)
{
    const int lane = threadIdx.x & 31;
    const int w = threadIdx.x >> 5;
    const int b = blockIdx.x * 4 + w;        // GRID*4 == BB

    // double-buffered per-warp broadcast of duplicated v
    __shared__ ulonglong2 sbuf[2][4][32];

    // ---- dtype self-detection (mask row 0 all-True since lengths >= 1) ----
    const unsigned char* m8 = (const unsigned char*)mask_raw;
    int mmode;  // 0 = u8, 1 = i32, 2 = f32
    if (m8[0] == 1 && m8[1] == 1)      mmode = 0;
    else if (m8[0] == 1)               mmode = 1;
    else                               mmode = 2;

    const int* t32p = (const int*)target_raw;
    int oddbits = 0;
#pragma unroll
    for (int i = 1; i < 16; i += 2) oddbits |= t32p[i];
    const int tmode = (oddbits == 0) ? 1 : 0;  // 1 = int64, 0 = int32

    // E2[j] = (exp(trans[j][2*lane]), exp(trans[j][2*lane+1])) packed
    ull E2[NN];
#pragma unroll
    for (int j = 0; j < NN; j++) {
        float2 tr = reinterpret_cast<const float2*>(trans)[j * 32 + lane];
        E2[j] = pack2(__expf(tr.x), __expf(tr.y));
    }

    const int len = seq_len(mask_raw, mmode, b, lane);

    const float2* emit2 = reinterpret_cast<const float2*>(emit);
    float2 st = reinterpret_cast<const float2*>(strans)[lane];
    float2 e0 = emit2[(size_t)b * 32 + lane];
    float ia0 = st.x + e0.x;               // alpha(0)[2*lane]
    float ia1 = st.y + e0.y;
    const float C0 = __shfl_sync(0xffffffffu, ia0, 0);   // initial common offset
    // linear-domain state: alpha_k(t) = log v_k + C0 + ln2 * stotal
    float v0 = __expf(ia0 - C0);
    float v1 = __expf(ia1 - C0);
    int stotal = 0;

    // prefetch ring holds PRE-EXPONENTIATED emissions (exp computed off-chain, PD steps early)
    float2 q[PD];
#pragma unroll
    for (int j = 0; j < PD; j++) {
        float2 e = emit2[((size_t)min(1 + j, TT - 1) * BB + b) * 32 + lane];
        q[j] = make_float2(__expf(e.x), __expf(e.y));
    }

    // lag-1 normalization reference: lane 0's v0 from the previous step
    float rref = __shfl_sync(0xffffffffu, v0, 0);   // == 1 at init

#define CRF_STEP(XM, TIDX)                                                     \
    {                                                                          \
        /* off-chain: scale = 2^(-s) from exponent bits of lagged reference */ \
        int sexp = ((__float_as_int(rref) >> 23) & 0xFF) - 127;                \
        stotal += sexp;                                                        \
        float scl = __int_as_float((127 - sexp) << 23);                        \
        ull mm = pack2((XM).x * scl, (XM).y * scl);                            \
        const int par = (TIDX) & 1;                                            \
        sbuf[par][w][lane] = make_ulonglong2(pack2(v0, v0), pack2(v1, v1));    \
        __syncwarp();                                                          \
        const ulonglong2* swp = sbuf[par][w];                                  \
        ull cA = 0, cB = 0, cC = 0, cD = 0;                                    \
        _Pragma("unroll")                                                      \
        for (int s = 0; s < 32; s += 2) {                                      \
            ulonglong2 u0 = swp[s], u1 = swp[s + 1];                           \
            cA = fma2(u0.x, E2[2 * s],     cA);                                \
            cB = fma2(u0.y, E2[2 * s + 1], cB);                                \
            cC = fma2(u1.x, E2[2 * s + 2], cC);                                \
            cD = fma2(u1.y, E2[2 * s + 3], cD);                                \
        }                                                                      \
        ull vv = mul2(add2(add2(cA, cB), add2(cC, cD)), mm);                   \
        unpack2(vv, v0, v1);                                                   \
        rref = __shfl_sync(0xffffffffu, v0, 0);  /* consumed next step */      \
    }

    int t = 1;
    for (; t + PD <= len; t += PD) {
#pragma unroll
        for (int j = 0; j < PD; j++) {
            float2 xm = q[j];
            float2 e = emit2[((size_t)min(t + PD + j, TT - 1) * BB + b) * 32 + lane];
            q[j] = make_float2(__expf(e.x), __expf(e.y));   // pre-exp at prefetch
            CRF_STEP(xm, t + j);
        }
    }
    for (int j = 0; t < len; t++, j++) {   // tail: q[j] holds slot t
        float2 xm = q[j];
        CRF_STEP(xm, t);
    }
#undef CRF_STEP

    // logZ_b = C0 + ln2*stotal + log( sum_k v_k * exp(etrans_k) )
    float2 et = reinterpret_cast<const float2*>(etrans)[lane];
    float wsum = v0 * __expf(et.x) + v1 * __expf(et.y);
#pragma unroll
    for (int o = 16; o; o >>= 1) wsum += __shfl_xor_sync(0xffffffffu, wsum, o);
    float logZ = C0 + 0.6931471805599453f * (float)stotal + __logf(wsum);

    float sc = gold_score(emit, trans, strans, etrans, target_raw, tmode, b, len, lane);
    if (lane == 0) g_partial[b] = logZ - sc;

    // ---- last-CTA-done deterministic reduction ----
    __shared__ float rsh[128];
    __shared__ int islast;
    __threadfence();
    __syncthreads();
    if (threadIdx.x == 0)
        islast = (atomicAdd(&g_count, 1) == GRID - 1);
    __syncthreads();
    if (islast) {
        __threadfence();
        float s = 0.f;
#pragma unroll
        for (int i = 0; i < BB / 128; i++)          // fixed order: deterministic
            s += g_partial[threadIdx.x + i * 128];
        rsh[threadIdx.x] = s;
        __syncthreads();
        for (int off = 64; off > 0; off >>= 1) {
            if (threadIdx.x < off) rsh[threadIdx.x] += rsh[threadIdx.x + off];
            __syncthreads();
        }
        if (threadIdx.x == 0) {
            out[0] = rsh[0] * (1.0f / BB);
            g_count = 0;                            // reset for next graph replay
        }
    }
}

extern "C" void kernel_launch(void* const* d_in, const int* in_sizes, int n_in,
                              void* d_out, int out_size) {
    const float* emit   = (const float*)d_in[0];
    const float* trans  = (const float*)d_in[1];
    const float* strans = (const float*)d_in[2];
    const float* etrans = (const float*)d_in[3];
    const void* target  = d_in[4];
    const void* mask    = d_in[5];

    crf_fused_kernel<<<GRID, 128>>>(emit, trans, strans, etrans, target, mask,
                                    (float*)d_out);
}

// round 8
// speedup vs baseline: 1.1016x; 1.0092x over previous
#include <cuda_runtime.h>

#define TT 512
#define BB 1024
#define NN 64
#define GRID 256
#define PD 4

__device__ float g_partial[BB];
__device__ int g_count = 0;

typedef unsigned long long ull;

// ---- packed f32x2 helpers (Blackwell) ----
__device__ __forceinline__ ull pack2(float x, float y) {
    ull r; asm("mov.b64 %0, {%1, %2};" : "=l"(r) : "f"(x), "f"(y)); return r;
}
__device__ __forceinline__ void unpack2(ull v, float& x, float& y) {
    asm("mov.b64 {%0, %1}, %2;" : "=f"(x), "=f"(y) : "l"(v));
}
__device__ __forceinline__ ull fma2(ull a, ull b, ull c) {
    ull d; asm("fma.rn.f32x2 %0, %1, %2, %3;" : "=l"(d) : "l"(a), "l"(b), "l"(c)); return d;
}
__device__ __forceinline__ ull add2(ull a, ull b) {
    ull d; asm("add.rn.f32x2 %0, %1, %2;" : "=l"(d) : "l"(a), "l"(b)); return d;
}
__device__ __forceinline__ ull mul2(ull a, ull b) {
    ull d; asm("mul.rn.f32x2 %0, %1, %2;" : "=l"(d) : "l"(a), "l"(b)); return d;
}

// cp.async 8B: no dest register -> ptxas cannot sink it; wait_group enforces distance
__device__ __forceinline__ void cp_async8(unsigned smem_addr, const void* gptr) {
    asm volatile("cp.async.ca.shared.global [%0], [%1], 8;" :: "r"(smem_addr), "l"(gptr));
}
__device__ __forceinline__ void cp_commit() {
    asm volatile("cp.async.commit_group;");
}
__device__ __forceinline__ void cp_wait_allbutPDm1() {
    asm volatile("cp.async.wait_group %0;" :: "n"(PD - 1));
}

__device__ __forceinline__ int seq_len(const void* mask_raw, int mmode, int b, int lane) {
    const unsigned char* m8 = (const unsigned char*)mask_raw;
    const int* m32 = (const int*)mask_raw;
    const float* mf = (const float*)mask_raw;
    int len = 0;
    if (mmode == 0) {
#pragma unroll 4
        for (int t = lane; t < TT; t += 32) len += (m8[(size_t)t * BB + b] != 0);
    } else if (mmode == 1) {
#pragma unroll 4
        for (int t = lane; t < TT; t += 32) len += (m32[(size_t)t * BB + b] != 0);
    } else {
#pragma unroll 4
        for (int t = lane; t < TT; t += 32) len += (mf[(size_t)t * BB + b] != 0.0f);
    }
#pragma unroll
    for (int o = 16; o; o >>= 1) len += __shfl_xor_sync(0xffffffffu, len, o);
    return len;
}

// gold-path score; result valid on lane 0
__device__ __forceinline__ float gold_score(
    const float* __restrict__ emit, const float* __restrict__ trans,
    const float* __restrict__ strans, const float* __restrict__ etrans,
    const void* __restrict__ traw, int tmode, int b, int len, int lane)
{
    const int* t32 = (const int*)traw;
    const long long* t64 = (const long long*)traw;
    float sc = 0.f;
    for (int i = lane; i < len; i += 32) {
        size_t idx = (size_t)i * BB + b;
        int tg = tmode ? (int)t64[idx] : t32[idx];
        sc += emit[idx * NN + tg];
        if (i > 0) {
            size_t p = (size_t)(i - 1) * BB + b;
            int pg = tmode ? (int)t64[p] : t32[p];
            sc += trans[pg * NN + tg];
        }
    }
#pragma unroll
    for (int o = 16; o; o >>= 1) sc += __shfl_xor_sync(0xffffffffu, sc, o);
    if (lane == 0) {
        int tg0 = tmode ? (int)t64[b] : t32[b];
        size_t li = (size_t)(len - 1) * BB + b;
        int tgl = tmode ? (int)t64[li] : t32[li];
        sc += strans[tg0] + etrans[tgl];
    }
    return sc;
}

__global__ void __launch_bounds__(128, 2) crf_fused_kernel(
    const float* __restrict__ emit,
    const float* __restrict__ trans,
    const float* __restrict__ strans,
    const float* __restrict__ etrans,
    const void* __restrict__ target_raw,
    const void* __restrict__ mask_raw,
    float* __restrict__ out)
{
    const int lane = threadIdx.x & 31;
    const int w = threadIdx.x >> 5;
    const int b = blockIdx.x * 4 + w;        // GRID*4 == BB

    __shared__ ulonglong2 sbuf[2][4][32];    // double-buffered v broadcast
    __shared__ float2 stage[4][PD][32];      // cp.async emit staging ring (per warp)

    // ---- dtype self-detection (mask row 0 all-True since lengths >= 1) ----
    const unsigned char* m8 = (const unsigned char*)mask_raw;
    int mmode;  // 0 = u8, 1 = i32, 2 = f32
    if (m8[0] == 1 && m8[1] == 1)      mmode = 0;
    else if (m8[0] == 1)               mmode = 1;
    else                               mmode = 2;

    const int* t32p = (const int*)target_raw;
    int oddbits = 0;
#pragma unroll
    for (int i = 1; i < 16; i += 2) oddbits |= t32p[i];
    const int tmode = (oddbits == 0) ? 1 : 0;  // 1 = int64, 0 = int32

    // E2[j] = (exp(trans[j][2*lane]), exp(trans[j][2*lane+1])) packed
    ull E2[NN];
#pragma unroll
    for (int j = 0; j < NN; j++) {
        float2 tr = reinterpret_cast<const float2*>(trans)[j * 32 + lane];
        E2[j] = pack2(__expf(tr.x), __expf(tr.y));
    }

    const int len = seq_len(mask_raw, mmode, b, lane);

    const float2* emit2 = reinterpret_cast<const float2*>(emit);
    float2 st = reinterpret_cast<const float2*>(strans)[lane];
    float2 e0 = emit2[(size_t)b * 32 + lane];
    float ia0 = st.x + e0.x;
    float ia1 = st.y + e0.y;
    const float C0 = __shfl_sync(0xffffffffu, ia0, 0);   // initial common offset
    // linear-domain state: alpha_k(t) = log v_k + C0 + ln2 * stotal
    float v0 = __expf(ia0 - C0);
    float v1 = __expf(ia1 - C0);
    int stotal = 0;

    // my staging slots (uint32 smem addresses for cp.async)
    unsigned stg_addr[PD];
#pragma unroll
    for (int j = 0; j < PD; j++)
        stg_addr[j] = (unsigned)__cvta_generic_to_shared(&stage[w][j][lane]);

    // prologue: fill the ring with steps t = 1..PD (clamped), one commit group each
#pragma unroll
    for (int j = 0; j < PD; j++) {
        cp_async8(stg_addr[j], &emit2[((size_t)min(1 + j, TT - 1) * BB + b) * 32 + lane]);
        cp_commit();
    }

    // lag-1 normalization reference: lane 0's v0 from the previous step
    float rref = __shfl_sync(0xffffffffu, v0, 0);   // == 1 at init

    for (int t = 1; t < len; t++) {
        const int slot = (t - 1) & (PD - 1);
        cp_wait_allbutPDm1();                        // slot for step t is complete
        float2 e = stage[w][slot][lane];
        // refill same slot for step t+PD (clamped; safe: data arrival lags LDS by >>29cyc)
        cp_async8(stg_addr[slot], &emit2[((size_t)min(t + PD, TT - 1) * BB + b) * 32 + lane]);
        cp_commit();

        // off-chain: normalization scale 2^(-s) from exponent bits of lagged reference
        int sexp = ((__float_as_int(rref) >> 23) & 0xFF) - 127;
        stotal += sexp;
        float scl = __int_as_float((127 - sexp) << 23);
        ull mm = pack2(__expf(e.x) * scl, __expf(e.y) * scl);

        const int par = t & 1;
        sbuf[par][w][lane] = make_ulonglong2(pack2(v0, v0), pack2(v1, v1));
        __syncwarp();
        const ulonglong2* swp = sbuf[par][w];
        ull c0 = 0, c1 = 0, c2 = 0, c3 = 0, c4 = 0, c5 = 0, c6 = 0, c7 = 0;
#pragma unroll
        for (int s = 0; s < 32; s += 4) {
            ulonglong2 u0 = swp[s],     u1 = swp[s + 1];
            ulonglong2 u2 = swp[s + 2], u3 = swp[s + 3];
            c0 = fma2(u0.x, E2[2 * s],     c0);
            c1 = fma2(u0.y, E2[2 * s + 1], c1);
            c2 = fma2(u1.x, E2[2 * s + 2], c2);
            c3 = fma2(u1.y, E2[2 * s + 3], c3);
            c4 = fma2(u2.x, E2[2 * s + 4], c4);
            c5 = fma2(u2.y, E2[2 * s + 5], c5);
            c6 = fma2(u3.x, E2[2 * s + 6], c6);
            c7 = fma2(u3.y, E2[2 * s + 7], c7);
        }
        ull vv = mul2(add2(add2(add2(c0, c1), add2(c2, c3)),
                           add2(add2(c4, c5), add2(c6, c7))), mm);
        unpack2(vv, v0, v1);
        rref = __shfl_sync(0xffffffffu, v0, 0);      // consumed next step
    }

    // logZ_b = C0 + ln2*stotal + log( sum_k v_k * exp(etrans_k) )
    float2 et = reinterpret_cast<const float2*>(etrans)[lane];
    float wsum = v0 * __expf(et.x) + v1 * __expf(et.y);
#pragma unroll
    for (int o = 16; o; o >>= 1) wsum += __shfl_xor_sync(0xffffffffu, wsum, o);
    float logZ = C0 + 0.6931471805599453f * (float)stotal + __logf(wsum);

    float sc = gold_score(emit, trans, strans, etrans, target_raw, tmode, b, len, lane);
    if (lane == 0) g_partial[b] = logZ - sc;

    // ---- last-CTA-done deterministic reduction ----
    __shared__ float rsh[128];
    __shared__ int islast;
    __threadfence();
    __syncthreads();
    if (threadIdx.x == 0)
        islast = (atomicAdd(&g_count, 1) == GRID - 1);
    __syncthreads();
    if (islast) {
        __threadfence();
        float s = 0.f;
#pragma unroll
        for (int i = 0; i < BB / 128; i++)          // fixed order: deterministic
            s += g_partial[threadIdx.x + i * 128];
        rsh[threadIdx.x] = s;
        __syncthreads();
        for (int off = 64; off > 0; off >>= 1) {
            if (threadIdx.x < off) rsh[threadIdx.x] += rsh[threadIdx.x + off];
            __syncthreads();
        }
        if (threadIdx.x == 0) {
            out[0] = rsh[0] * (1.0f / BB);
            g_count = 0;                            // reset for next graph replay
        }
    }
}

extern "C" void kernel_launch(void* const* d_in, const int* in_sizes, int n_in,
                              void* d_out, int out_size) {
    const float* emit   = (const float*)d_in[0];
    const float* trans  = (const float*)d_in[1];
    const float* strans = (const float*)d_in[2];
    const float* etrans = (const float*)d_in[3];
    const void* target  = d_in[4];
    const void* mask    = d_in[5];

    crf_fused_kernel<<<GRID, 128>>>(emit, trans, strans, etrans, target, mask,
                                    (float*)d_out);
}

// round 9
// speedup vs baseline: 1.2378x; 1.1236x over previous
#include <cuda_runtime.h>

#define TT 512
#define BB 1024
#define NN 64
#define GRID 256
#define PD 4

__device__ float g_partial[BB];
__device__ int g_count = 0;

typedef unsigned long long ull;

// ---- packed f32x2 helpers (Blackwell) ----
__device__ __forceinline__ ull pack2(float x, float y) {
    ull r; asm("mov.b64 %0, {%1, %2};" : "=l"(r) : "f"(x), "f"(y)); return r;
}
__device__ __forceinline__ void unpack2(ull v, float& x, float& y) {
    asm("mov.b64 {%0, %1}, %2;" : "=f"(x), "=f"(y) : "l"(v));
}
__device__ __forceinline__ ull fma2(ull a, ull b, ull c) {
    ull d; asm("fma.rn.f32x2 %0, %1, %2, %3;" : "=l"(d) : "l"(a), "l"(b), "l"(c)); return d;
}
__device__ __forceinline__ ull add2(ull a, ull b) {
    ull d; asm("add.rn.f32x2 %0, %1, %2;" : "=l"(d) : "l"(a), "l"(b)); return d;
}

// cp.async 8B: no dest register -> ptxas cannot sink it; wait_group enforces distance
__device__ __forceinline__ void cp_async8(unsigned smem_addr, const void* gptr) {
    asm volatile("cp.async.ca.shared.global [%0], [%1], 8;" :: "r"(smem_addr), "l"(gptr));
}
__device__ __forceinline__ void cp_commit() {
    asm volatile("cp.async.commit_group;");
}
__device__ __forceinline__ void cp_wait_allbutPDm1() {
    asm volatile("cp.async.wait_group %0;" :: "n"(PD - 1));
}

__device__ __forceinline__ int seq_len(const void* mask_raw, int mmode, int b, int lane) {
    const unsigned char* m8 = (const unsigned char*)mask_raw;
    const int* m32 = (const int*)mask_raw;
    const float* mf = (const float*)mask_raw;
    int len = 0;
    if (mmode == 0) {
#pragma unroll 4
        for (int t = lane; t < TT; t += 32) len += (m8[(size_t)t * BB + b] != 0);
    } else if (mmode == 1) {
#pragma unroll 4
        for (int t = lane; t < TT; t += 32) len += (m32[(size_t)t * BB + b] != 0);
    } else {
#pragma unroll 4
        for (int t = lane; t < TT; t += 32) len += (mf[(size_t)t * BB + b] != 0.0f);
    }
#pragma unroll
    for (int o = 16; o; o >>= 1) len += __shfl_xor_sync(0xffffffffu, len, o);
    return len;
}

// gold-path score; result valid on lane 0
__device__ __forceinline__ float gold_score(
    const float* __restrict__ emit, const float* __restrict__ trans,
    const float* __restrict__ strans, const float* __restrict__ etrans,
    const void* __restrict__ traw, int tmode, int b, int len, int lane)
{
    const int* t32 = (const int*)traw;
    const long long* t64 = (const long long*)traw;
    float sc = 0.f;
    for (int i = lane; i < len; i += 32) {
        size_t idx = (size_t)i * BB + b;
        int tg = tmode ? (int)t64[idx] : t32[idx];
        sc += emit[idx * NN + tg];
        if (i > 0) {
            size_t p = (size_t)(i - 1) * BB + b;
            int pg = tmode ? (int)t64[p] : t32[p];
            sc += trans[pg * NN + tg];
        }
    }
#pragma unroll
    for (int o = 16; o; o >>= 1) sc += __shfl_xor_sync(0xffffffffu, sc, o);
    if (lane == 0) {
        int tg0 = tmode ? (int)t64[b] : t32[b];
        size_t li = (size_t)(len - 1) * BB + b;
        int tgl = tmode ? (int)t64[li] : t32[li];
        sc += strans[tg0] + etrans[tgl];
    }
    return sc;
}

__global__ void __launch_bounds__(128, 2) crf_fused_kernel(
    const float* __restrict__ emit,
    const float* __restrict__ trans,
    const float* __restrict__ strans,
    const float* __restrict__ etrans,
    const void* __restrict__ target_raw,
    const void* __restrict__ mask_raw,
    float* __restrict__ out)
{
    const int lane = threadIdx.x & 31;
    const int w = threadIdx.x >> 5;
    const int b = blockIdx.x * 4 + w;        // GRID*4 == BB

    // double-buffered NON-duplicated v broadcast: 32 ull (256B) per warp per parity
    __shared__ __align__(16) ull sbufv[2][4][32];
    __shared__ float2 stage[4][PD][32];      // cp.async emit staging ring (per warp)

    // ---- dtype self-detection (mask row 0 all-True since lengths >= 1) ----
    const unsigned char* m8 = (const unsigned char*)mask_raw;
    int mmode;  // 0 = u8, 1 = i32, 2 = f32
    if (m8[0] == 1 && m8[1] == 1)      mmode = 0;
    else if (m8[0] == 1)               mmode = 1;
    else                               mmode = 2;

    const int* t32p = (const int*)target_raw;
    int oddbits = 0;
#pragma unroll
    for (int i = 1; i < 16; i += 2) oddbits |= t32p[i];
    const int tmode = (oddbits == 0) ? 1 : 0;  // 1 = int64, 0 = int32

    // E repacked over j-pairs for this lane's two output columns k0=2*lane, k1=2*lane+1:
    //   Ek0[p] = (exp(trans[2p][k0]), exp(trans[2p+1][k0]))
    //   Ek1[p] = (exp(trans[2p][k1]), exp(trans[2p+1][k1]))
    const int k0 = 2 * lane, k1 = 2 * lane + 1;
    ull Ek0[32], Ek1[32];
#pragma unroll
    for (int p = 0; p < 32; p++) {
        float t00 = trans[(2 * p) * NN + k0],     t10 = trans[(2 * p + 1) * NN + k0];
        float t01 = trans[(2 * p) * NN + k1],     t11 = trans[(2 * p + 1) * NN + k1];
        Ek0[p] = pack2(__expf(t00), __expf(t10));
        Ek1[p] = pack2(__expf(t01), __expf(t11));
    }

    const int len = seq_len(mask_raw, mmode, b, lane);

    const float2* emit2 = reinterpret_cast<const float2*>(emit);
    float2 st = reinterpret_cast<const float2*>(strans)[lane];
    float2 e0 = emit2[(size_t)b * 32 + lane];
    float ia0 = st.x + e0.x;
    float ia1 = st.y + e0.y;
    const float C0 = __shfl_sync(0xffffffffu, ia0, 0);   // initial common offset
    // linear-domain state: alpha_k(t) = log v_k + C0 + ln2 * stotal
    float v0 = __expf(ia0 - C0);
    float v1 = __expf(ia1 - C0);
    int stotal = 0;

    // staging slot addresses for cp.async
    unsigned stg_addr[PD];
#pragma unroll
    for (int j = 0; j < PD; j++)
        stg_addr[j] = (unsigned)__cvta_generic_to_shared(&stage[w][j][lane]);

    // prologue: fill ring with steps t = 1..PD (clamped), one commit group each
#pragma unroll
    for (int j = 0; j < PD; j++) {
        cp_async8(stg_addr[j], &emit2[((size_t)min(1 + j, TT - 1) * BB + b) * 32 + lane]);
        cp_commit();
    }

    // lag-1 normalization reference: lane 0's v0 from the previous step
    float rref = __shfl_sync(0xffffffffu, v0, 0);   // == 1 at init

    for (int t = 1; t < len; t++) {
        const int slot = (t - 1) & (PD - 1);
        cp_wait_allbutPDm1();                        // slot for step t complete
        float2 e = stage[w][slot][lane];
        cp_async8(stg_addr[slot], &emit2[((size_t)min(t + PD, TT - 1) * BB + b) * 32 + lane]);
        cp_commit();

        // off-chain: normalization scale 2^(-s) from exponent bits of lagged reference
        int sexp = ((__float_as_int(rref) >> 23) & 0xFF) - 127;
        stotal += sexp;
        float scl = __int_as_float((127 - sexp) << 23);
        float mx = __expf(e.x) * scl, my = __expf(e.y) * scl;

        // publish natural (non-duplicated) state pair: lane == pair index
        const int par = t & 1;
        sbufv[par][w][lane] = pack2(v0, v1);
        __syncwarp();
        const ulonglong2* vv = reinterpret_cast<const ulonglong2*>(sbufv[par][w]);

        // c_k = sum_p  vpair_p .* Ecol_k[p]  (fma2 over j-pairs; horizontal add at end)
        ull a0 = 0, a1 = 0, a2 = 0, a3 = 0;   // column k0 partials
        ull b0 = 0, b1 = 0, b2 = 0, b3 = 0;   // column k1 partials
#pragma unroll
        for (int p = 0; p < 32; p += 4) {
            ulonglong2 q0 = vv[p / 2];        // broadcast LDS.128: vpairs p, p+1
            ulonglong2 q1 = vv[p / 2 + 1];    // vpairs p+2, p+3
            a0 = fma2(q0.x, Ek0[p],     a0);
            b0 = fma2(q0.x, Ek1[p],     b0);
            a1 = fma2(q0.y, Ek0[p + 1], a1);
            b1 = fma2(q0.y, Ek1[p + 1], b1);
            a2 = fma2(q1.x, Ek0[p + 2], a2);
            b2 = fma2(q1.x, Ek1[p + 2], b2);
            a3 = fma2(q1.y, Ek0[p + 3], a3);
            b3 = fma2(q1.y, Ek1[p + 3], b3);
        }
        float ax, ay, bx, by;
        unpack2(add2(add2(a0, a1), add2(a2, a3)), ax, ay);
        unpack2(add2(add2(b0, b1), add2(b2, b3)), bx, by);
        v0 = (ax + ay) * mx;                  // new v for state k0
        v1 = (bx + by) * my;                  // new v for state k1
        rref = __shfl_sync(0xffffffffu, v0, 0);   // consumed next step
    }

    // logZ_b = C0 + ln2*stotal + log( sum_k v_k * exp(etrans_k) )
    float2 et = reinterpret_cast<const float2*>(etrans)[lane];
    float wsum = v0 * __expf(et.x) + v1 * __expf(et.y);
#pragma unroll
    for (int o = 16; o; o >>= 1) wsum += __shfl_xor_sync(0xffffffffu, wsum, o);
    float logZ = C0 + 0.6931471805599453f * (float)stotal + __logf(wsum);

    float sc = gold_score(emit, trans, strans, etrans, target_raw, tmode, b, len, lane);
    if (lane == 0) g_partial[b] = logZ - sc;

    // ---- last-CTA-done deterministic reduction ----
    __shared__ float rsh[128];
    __shared__ int islast;
    __threadfence();
    __syncthreads();
    if (threadIdx.x == 0)
        islast = (atomicAdd(&g_count, 1) == GRID - 1);
    __syncthreads();
    if (islast) {
        __threadfence();
        float s = 0.f;
#pragma unroll
        for (int i = 0; i < BB / 128; i++)          // fixed order: deterministic
            s += g_partial[threadIdx.x + i * 128];
        rsh[threadIdx.x] = s;
        __syncthreads();
        for (int off = 64; off > 0; off >>= 1) {
            if (threadIdx.x < off) rsh[threadIdx.x] += rsh[threadIdx.x + off];
            __syncthreads();
        }
        if (threadIdx.x == 0) {
            out[0] = rsh[0] * (1.0f / BB);
            g_count = 0;                            // reset for next graph replay
        }
    }
}

extern "C" void kernel_launch(void* const* d_in, const int* in_sizes, int n_in,
                              void* d_out, int out_size) {
    const float* emit   = (const float*)d_in[0];
    const float* trans  = (const float*)d_in[1];
    const float* strans = (const float*)d_in[2];
    const float* etrans = (const float*)d_in[3];
    const void* target  = d_in[4];
    const void* mask    = d_in[5];

    crf_fused_kernel<<<GRID, 128>>>(emit, trans, strans, etrans, target, mask,
                                    (float*)d_out);
}